// round 3
// baseline (speedup 1.0000x reference)
#include <cuda_runtime.h>

#define NN 50000
#define HH 256
#define EE 320000
#define NL 5

// ---------------- scratch (static __device__, no allocation) ----------------
__device__ __align__(16) float g_h[2][NN * HH];   // ping-pong node features
__device__ __align__(16) float g_agg[NN * HH];    // per-layer aggregation
__device__ int   g_deg[NN];
__device__ int   g_cur[NN];
__device__ int   g_off[NN];
__device__ float g_dinv[NN];
__device__ int   g_src[EE];
__device__ float g_w[EE];
__device__ __align__(16) float g_s4[NN * 4];      // per-node sum of norm*edge_attr
__device__ __align__(16) float g_bnsum[NL * HH];
__device__ __align__(16) float g_bnsq[NL * HH];
__device__ int   g_is64;                          // edge_index dtype flag

// ---------------- setup kernels ----------------
__global__ void zero_kernel() {
    int i = blockIdx.x * blockDim.x + threadIdx.x;
    if (i == 0) g_is64 = 1;
    if (i < NN) { g_deg[i] = 0; g_cur[i] = 0; }
    if (i < NN * 4) g_s4[i] = 0.f;
    if (i < NL * HH) { g_bnsum[i] = 0.f; g_bnsq[i] = 0.f; }
}

// Probe dtype of edge_index: read only the first EE u64 words (= the int32
// allocation size), so no OOB either way. True int64 indices are all < NN;
// int32 data misread as u64 is >= 2^32 for ~every word.
__global__ void detect_kernel(const unsigned long long* __restrict__ p) {
    int e = blockIdx.x * blockDim.x + threadIdx.x;
    if (e < EE) {
        if (p[e] >= (unsigned long long)NN) g_is64 = 0;
    }
}

__global__ void deg_kernel(const void* __restrict__ eiv) {
    int e = blockIdx.x * blockDim.x + threadIdx.x;
    if (e >= EE) return;
    int c;
    if (g_is64) c = (int)((const long long*)eiv)[EE + e];
    else        c = ((const int*)eiv)[EE + e];
    if (c >= 0 && c < NN) atomicAdd(&g_deg[c], 1);
}

__global__ void dinv_kernel() {
    int i = blockIdx.x * blockDim.x + threadIdx.x;
    if (i < NN) {
        int d = g_deg[i];
        g_dinv[i] = (d > 0) ? rsqrtf((float)d) : 0.f;
    }
}

// exclusive scan of g_deg -> g_off (single block, 1024 threads)
__global__ void scan_kernel() {
    __shared__ int ts[1024];
    int t = threadIdx.x;
    const int CH = (NN + 1023) / 1024;
    int beg = t * CH;
    int end = min(beg + CH, NN);
    int s = 0;
    for (int i = beg; i < end; i++) s += g_deg[i];
    ts[t] = s;
    __syncthreads();
    for (int off = 1; off < 1024; off <<= 1) {
        int v = (t >= off) ? ts[t - off] : 0;
        __syncthreads();
        ts[t] += v;
        __syncthreads();
    }
    int run = (t == 0) ? 0 : ts[t - 1];
    for (int i = beg; i < end; i++) { g_off[i] = run; run += g_deg[i]; }
}

__global__ void place_kernel(const void* __restrict__ eiv,
                             const float* __restrict__ ea) {
    int e = blockIdx.x * blockDim.x + threadIdx.x;
    if (e >= EE) return;
    int r, c;
    if (g_is64) {
        r = (int)((const long long*)eiv)[e];
        c = (int)((const long long*)eiv)[EE + e];
    } else {
        r = ((const int*)eiv)[e];
        c = ((const int*)eiv)[EE + e];
    }
    if (r < 0 || r >= NN || c < 0 || c >= NN) return;
    float w = g_dinv[r] * g_dinv[c];
    int slot = g_off[c] + atomicAdd(&g_cur[c], 1);
    g_src[slot] = r;
    g_w[slot] = w;
    atomicAdd(&g_s4[c * 4 + 0], w * ea[e * 4 + 0]);
    atomicAdd(&g_s4[c * 4 + 1], w * ea[e * 4 + 1]);
    atomicAdd(&g_s4[c * 4 + 2], w * ea[e * 4 + 2]);
    atomicAdd(&g_s4[c * 4 + 3], w * ea[e * 4 + 3]);
}

// ---------------- aggregation: one warp per node ----------------
__global__ __launch_bounds__(256) void agg_kernel(
    const float* __restrict__ xExt, int prevSel,
    const float* __restrict__ ew1l, const float* __restrict__ ew2l)
{
    int gw = (blockIdx.x * 256 + threadIdx.x) >> 5;
    int lane = threadIdx.x & 31;
    if (gw >= NN) return;
    const float* h = (prevSel == 0) ? xExt : g_h[prevSel - 1];
    const float4* h4 = (const float4*)h;

    int beg = g_off[gw];
    int cnt = g_deg[gw];
    float4 a0 = make_float4(0.f, 0.f, 0.f, 0.f);
    float4 a1 = make_float4(0.f, 0.f, 0.f, 0.f);
    for (int i = beg; i < beg + cnt; i++) {
        int src = __ldg(&g_src[i]);
        float w = __ldg(&g_w[i]);
        float4 v0 = h4[src * 64 + lane];
        float4 v1 = h4[src * 64 + 32 + lane];
        a0.x = fmaf(w, v0.x, a0.x); a0.y = fmaf(w, v0.y, a0.y);
        a0.z = fmaf(w, v0.z, a0.z); a0.w = fmaf(w, v0.w, a0.w);
        a1.x = fmaf(w, v1.x, a1.x); a1.y = fmaf(w, v1.y, a1.y);
        a1.z = fmaf(w, v1.z, a1.z); a1.w = fmaf(w, v1.w, a1.w);
    }
    // folded edge-feature term
    float s0 = g_s4[gw * 4 + 0], s1 = g_s4[gw * 4 + 1];
    float s2 = g_s4[gw * 4 + 2], s3 = g_s4[gw * 4 + 3];
    float4 e1 = ((const float4*)ew1l)[lane];
    a0.x = fmaf(s3, e1.x, a0.x); a0.y = fmaf(s3, e1.y, a0.y);
    a0.z = fmaf(s3, e1.z, a0.z); a0.w = fmaf(s3, e1.w, a0.w);
    float4 w0 = ((const float4*)(ew2l))[lane];
    float4 w1 = ((const float4*)(ew2l + 128))[lane];
    float4 w2 = ((const float4*)(ew2l + 256))[lane];
    a1.x = fmaf(s0, w0.x, fmaf(s1, w1.x, fmaf(s2, w2.x, a1.x)));
    a1.y = fmaf(s0, w0.y, fmaf(s1, w1.y, fmaf(s2, w2.y, a1.y)));
    a1.z = fmaf(s0, w0.z, fmaf(s1, w1.z, fmaf(s2, w2.z, a1.z)));
    a1.w = fmaf(s0, w0.w, fmaf(s1, w1.w, fmaf(s2, w2.w, a1.w)));

    float4* o = (float4*)g_agg;
    o[gw * 64 + lane] = a0;
    o[gw * 64 + 32 + lane] = a1;
}

// ---------------- GEMM: C = relu([h | agg] @ W + b), with BN partial stats ----
// 128x128 tile, K-chunk 8, 8x8 per thread, plain fmaf accumulation
__global__ __launch_bounds__(256) void gemm_kernel(
    const float* __restrict__ xExt, int prevSel, int cur,
    const float* __restrict__ W, const float* __restrict__ bias, int l)
{
    __shared__ float As[8][128];
    __shared__ float Bs[8][128];
    const float* Ah = (prevSel == 0) ? xExt : g_h[prevSel - 1];
    const float* Ag = g_agg;
    float* C = g_h[cur];

    int tid = threadIdx.x;
    int n0 = blockIdx.x * 128;
    int m0 = blockIdx.y * 128;
    int tx = tid & 15, ty = tid >> 4;
    int mSub = ty * 8, nSub = tx * 8;

    float acc[8][8];
#pragma unroll
    for (int i = 0; i < 8; i++)
#pragma unroll
        for (int j = 0; j < 8; j++) acc[i][j] = 0.f;

    int lm = tid >> 1;
    int lk = (tid & 1) * 4;
    int bkr = tid >> 5;
    int bn4 = (tid & 31) * 4;
    int arow = m0 + lm;

    for (int k0 = 0; k0 < 2 * HH; k0 += 8) {
        float4 av = make_float4(0.f, 0.f, 0.f, 0.f);
        if (arow < NN) {
            int k = k0 + lk;
            const float* s = (k < HH) ? (Ah + arow * HH + k)
                                      : (Ag + arow * HH + (k - HH));
            av = *(const float4*)s;
        }
        As[lk + 0][lm] = av.x;
        As[lk + 1][lm] = av.y;
        As[lk + 2][lm] = av.z;
        As[lk + 3][lm] = av.w;
        *(float4*)&Bs[bkr][bn4] = *(const float4*)(W + (k0 + bkr) * HH + n0 + bn4);
        __syncthreads();
#pragma unroll
        for (int kk = 0; kk < 8; kk++) {
            float4 a0 = *(const float4*)&As[kk][mSub];
            float4 a1 = *(const float4*)&As[kk][mSub + 4];
            float4 b0 = *(const float4*)&Bs[kk][nSub];
            float4 b1 = *(const float4*)&Bs[kk][nSub + 4];
            float ar[8] = {a0.x, a0.y, a0.z, a0.w, a1.x, a1.y, a1.z, a1.w};
            float br[8] = {b0.x, b0.y, b0.z, b0.w, b1.x, b1.y, b1.z, b1.w};
#pragma unroll
            for (int i = 0; i < 8; i++)
#pragma unroll
                for (int j = 0; j < 8; j++)
                    acc[i][j] = fmaf(ar[i], br[j], acc[i][j]);
        }
        __syncthreads();
    }

    float4 bb0 = *(const float4*)(bias + n0 + nSub);
    float4 bb1 = *(const float4*)(bias + n0 + nSub + 4);
    float br[8] = {bb0.x, bb0.y, bb0.z, bb0.w, bb1.x, bb1.y, bb1.z, bb1.w};
    float colSum[8], colSq[8];
#pragma unroll
    for (int j = 0; j < 8; j++) { colSum[j] = 0.f; colSq[j] = 0.f; }

#pragma unroll
    for (int i = 0; i < 8; i++) {
        int row = m0 + mSub + i;
        if (row < NN) {
            float o[8];
#pragma unroll
            for (int j = 0; j < 8; j++) {
                float v = fmaxf(acc[i][j] + br[j], 0.f);
                o[j] = v;
                colSum[j] += v;
                colSq[j] += v * v;
            }
            *(float4*)&C[row * HH + n0 + nSub] =
                make_float4(o[0], o[1], o[2], o[3]);
            *(float4*)&C[row * HH + n0 + nSub + 4] =
                make_float4(o[4], o[5], o[6], o[7]);
        }
    }

    // block-level BN partial reduction (reuse As as 256-float scratch)
    __syncthreads();
    float* red = &As[0][0];
    red[tid] = 0.f;
    __syncthreads();
#pragma unroll
    for (int j = 0; j < 8; j++) {
        atomicAdd(&red[nSub + j], colSum[j]);
        atomicAdd(&red[128 + nSub + j], colSq[j]);
    }
    __syncthreads();
    if (tid < 128) {
        atomicAdd(&g_bnsum[l * HH + n0 + tid], red[tid]);
        atomicAdd(&g_bnsq[l * HH + n0 + tid], red[128 + tid]);
    }
}

// ---------------- BN apply (+ optional relu) ----------------
__global__ __launch_bounds__(256) void bn_kernel(
    int cur, int l, const float* __restrict__ gm, const float* __restrict__ bt,
    float* __restrict__ dout, int last)
{
    int idx = blockIdx.x * blockDim.x + threadIdx.x;
    if (idx >= NN * 64) return;
    int c4 = idx & 63;
    const float4* S = (const float4*)(g_bnsum + l * HH);
    const float4* Q = (const float4*)(g_bnsq + l * HH);
    float4 s = S[c4], q = Q[c4];
    const float invN = 1.0f / (float)NN;
    float4 mu = make_float4(s.x * invN, s.y * invN, s.z * invN, s.w * invN);
    float4 iv;
    iv.x = rsqrtf(fmaf(-mu.x, mu.x, q.x * invN) + 1e-5f);
    iv.y = rsqrtf(fmaf(-mu.y, mu.y, q.y * invN) + 1e-5f);
    iv.z = rsqrtf(fmaf(-mu.z, mu.z, q.z * invN) + 1e-5f);
    iv.w = rsqrtf(fmaf(-mu.w, mu.w, q.w * invN) + 1e-5f);
    float4 g4 = ((const float4*)gm)[c4];
    float4 b4 = ((const float4*)bt)[c4];
    float4 x = ((const float4*)g_h[cur])[idx];
    float4 y;
    y.x = fmaf((x.x - mu.x) * iv.x, g4.x, b4.x);
    y.y = fmaf((x.y - mu.y) * iv.y, g4.y, b4.y);
    y.z = fmaf((x.z - mu.z) * iv.z, g4.z, b4.z);
    y.w = fmaf((x.w - mu.w) * iv.w, g4.w, b4.w);
    if (!last) {
        y.x = fmaxf(y.x, 0.f); y.y = fmaxf(y.y, 0.f);
        y.z = fmaxf(y.z, 0.f); y.w = fmaxf(y.w, 0.f);
    }
    float4* o = last ? (float4*)dout : (float4*)g_h[cur];
    o[idx] = y;
}

// ---------------- launch ----------------
extern "C" void kernel_launch(void* const* d_in, const int* in_sizes, int n_in,
                              void* d_out, int out_size)
{
    const float* x   = (const float*)d_in[0];
    const void*  ei  = d_in[1];
    const float* ea  = (const float*)d_in[2];
    const float* mw  = (const float*)d_in[3];
    const float* mb  = (const float*)d_in[4];
    const float* ew1 = (const float*)d_in[5];
    const float* ew2 = (const float*)d_in[6];
    const float* bg  = (const float*)d_in[7];
    const float* bb  = (const float*)d_in[8];
    float* out = (float*)d_out;

    zero_kernel<<<(NN * 4 + 255) / 256, 256>>>();
    detect_kernel<<<(EE + 255) / 256, 256>>>(
        (const unsigned long long*)ei);
    deg_kernel<<<(EE + 255) / 256, 256>>>(ei);
    dinv_kernel<<<(NN + 255) / 256, 256>>>();
    scan_kernel<<<1, 1024>>>();
    place_kernel<<<(EE + 255) / 256, 256>>>(ei, ea);

    for (int l = 0; l < NL; l++) {
        int cur = l & 1;
        int prevSel = (l == 0) ? 0 : (((l - 1) & 1) + 1);
        agg_kernel<<<(NN + 7) / 8, 256>>>(x, prevSel,
                                          ew1 + l * (HH / 2),
                                          ew2 + l * 3 * (HH / 2));
        dim3 gg(2, (NN + 127) / 128);
        gemm_kernel<<<gg, 256>>>(x, prevSel, cur,
                                 mw + (size_t)l * 2 * HH * HH,
                                 mb + l * HH, l);
        bn_kernel<<<(NN * 64 + 255) / 256, 256>>>(
            cur, l, bg + l * HH, bb + l * HH, out, (l == NL - 1) ? 1 : 0);
    }
}